// round 3
// baseline (speedup 1.0000x reference)
#include <cuda_runtime.h>
#include <math.h>

// Problem constants (fixed by reference)
#define BB 2
#define LL 2048
#define DM 1024
#define DI 2048
#define DS 16
#define DR 64
#define NR (BB*LL)     // 4096 rows (b,l)
#define XZW (2*DI)     // 4096
#define XD  96         // dt_rank + 2*d_state

// Scratch (device globals; no allocation allowed)
__device__ float g_xz  [(size_t)NR*XZW];   // in_proj output [B,L,2*DI]
__device__ float g_xp  [(size_t)NR*DI];    // conv+silu output [B,L,DI]
__device__ float g_xpt [(size_t)BB*DI*LL]; // conv+silu output transposed [B,DI,L]
__device__ float g_xdbl[(size_t)NR*XD];    // x_proj output [B,L,96]
__device__ float g_dtt [(size_t)BB*DI*LL]; // softplus(delta) transposed [B,DI,L]
__device__ float g_yt  [(size_t)BB*DI*LL]; // scan output (+D*x) [B,DI,L]
__device__ float g_g   [(size_t)NR*DI];    // y * silu(z) [B,L,DI]

__device__ __forceinline__ float siluf(float x) { return x / (1.0f + __expf(-x)); }
__device__ __forceinline__ float softplusf(float x) {
    return (x > 20.0f) ? x : log1pf(__expf(x));
}

// ---------------------------------------------------------------------------
// Generic NT SGEMM: C[M,N] = A[M,K] * B[N,K]^T, all row-major, dims % tile == 0
// 128x128x16 tiles, 256 threads, 8x8 micro-tile.
// ---------------------------------------------------------------------------
__global__ __launch_bounds__(256, 2)
void gemm_nt_128(const float* __restrict__ A, const float* __restrict__ Bm,
                 float* __restrict__ C, int M, int N, int K)
{
    __shared__ float As[16][132];
    __shared__ float Bs[16][132];
    const int tid = threadIdx.x;
    const int m0 = blockIdx.y * 128;
    const int n0 = blockIdx.x * 128;
    const int tx = tid & 15, ty = tid >> 4;
    const int lr = tid >> 2;           // 0..63
    const int lc = (tid & 3) << 2;     // 0,4,8,12

    float acc[8][8];
    #pragma unroll
    for (int i = 0; i < 8; ++i)
        #pragma unroll
        for (int j = 0; j < 8; ++j) acc[i][j] = 0.0f;

    for (int k0 = 0; k0 < K; k0 += 16) {
        #pragma unroll
        for (int p = 0; p < 2; ++p) {
            int r = lr + p * 64;
            float4 va = *(const float4*)(A + (size_t)(m0 + r) * K + k0 + lc);
            As[lc+0][r] = va.x; As[lc+1][r] = va.y; As[lc+2][r] = va.z; As[lc+3][r] = va.w;
            float4 vb = *(const float4*)(Bm + (size_t)(n0 + r) * K + k0 + lc);
            Bs[lc+0][r] = vb.x; Bs[lc+1][r] = vb.y; Bs[lc+2][r] = vb.z; Bs[lc+3][r] = vb.w;
        }
        __syncthreads();
        #pragma unroll
        for (int k = 0; k < 16; ++k) {
            float a[8], b[8];
            *(float4*)(a)     = *(const float4*)&As[k][ty*8];
            *(float4*)(a + 4) = *(const float4*)&As[k][ty*8 + 4];
            *(float4*)(b)     = *(const float4*)&Bs[k][tx*8];
            *(float4*)(b + 4) = *(const float4*)&Bs[k][tx*8 + 4];
            #pragma unroll
            for (int i = 0; i < 8; ++i)
                #pragma unroll
                for (int j = 0; j < 8; ++j)
                    acc[i][j] = fmaf(a[i], b[j], acc[i][j]);
        }
        __syncthreads();
    }
    #pragma unroll
    for (int i = 0; i < 8; ++i) {
        float* cp = C + (size_t)(m0 + ty*8 + i) * N + n0 + tx*8;
        *(float4*)(cp)     = make_float4(acc[i][0], acc[i][1], acc[i][2], acc[i][3]);
        *(float4*)(cp + 4) = make_float4(acc[i][4], acc[i][5], acc[i][6], acc[i][7]);
    }
}

// ---------------------------------------------------------------------------
// Causal depthwise conv (width 4) + bias + silu over xz[:, :, 0:DI].
// Writes g_xp [B,L,DI] and transposed g_xpt [B,DI,L].
// Grid: (L/32, DI/32, B), 256 threads.
// ---------------------------------------------------------------------------
__global__ void conv_silu_kernel(const float* __restrict__ conv_w,
                                 const float* __restrict__ conv_b)
{
    __shared__ float sIn[35][33];
    __shared__ float sOut[32][33];
    const int b = blockIdx.z, d0 = blockIdx.y * 32, l0 = blockIdx.x * 32;
    const int tid = threadIdx.x, tx = tid & 31, ty = tid >> 5;

    for (int r = ty; r < 35; r += 8) {
        int gl = l0 + r - 3;
        sIn[r][tx] = (gl >= 0) ? g_xz[(size_t)(b*LL + gl) * XZW + d0 + tx] : 0.0f;
    }
    __syncthreads();

    float4 w = *(const float4*)(conv_w + (d0 + tx) * 4);
    float cb = conv_b[d0 + tx];
    #pragma unroll
    for (int i = 0; i < 4; ++i) {
        int r = ty + i * 8;
        float v = sIn[r][tx]*w.x + sIn[r+1][tx]*w.y + sIn[r+2][tx]*w.z + sIn[r+3][tx]*w.w + cb;
        v = siluf(v);
        sOut[r][tx] = v;
        g_xp[(size_t)(b*LL + l0 + r) * DI + d0 + tx] = v;
    }
    __syncthreads();
    #pragma unroll
    for (int i = 0; i < 4; ++i) {
        int dd = ty + i * 8;
        g_xpt[(size_t)(b*DI + d0 + dd) * LL + l0 + tx] = sOut[tx][dd];
    }
}

// ---------------------------------------------------------------------------
// x_dbl = x_p @ x_proj_w^T : [4096, 2048] x [96, 2048]^T -> [4096, 96]
// 64(M) x 96(N, full) x 32(K) tiles.
// ---------------------------------------------------------------------------
__global__ __launch_bounds__(256)
void gemm_xproj(const float* __restrict__ xw)
{
    __shared__ float As[32][68];
    __shared__ float Bs[32][100];
    const int tid = threadIdx.x;
    const int m0 = blockIdx.x * 64;
    const int tx = tid & 15, ty = tid >> 4;

    float acc[4][6];
    #pragma unroll
    for (int i = 0; i < 4; ++i)
        #pragma unroll
        for (int j = 0; j < 6; ++j) acc[i][j] = 0.0f;

    for (int k0 = 0; k0 < DI; k0 += 32) {
        #pragma unroll
        for (int p = 0; p < 2; ++p) {
            int idx = tid + p * 256;
            int r = idx >> 3, c4 = (idx & 7) << 2;
            float4 v = *(const float4*)(g_xp + (size_t)(m0 + r) * DI + k0 + c4);
            As[c4+0][r] = v.x; As[c4+1][r] = v.y; As[c4+2][r] = v.z; As[c4+3][r] = v.w;
        }
        #pragma unroll
        for (int p = 0; p < 3; ++p) {
            int idx = tid + p * 256;
            int r = idx >> 3, c4 = (idx & 7) << 2;   // r in 0..95
            float4 v = *(const float4*)(xw + (size_t)r * DI + k0 + c4);
            Bs[c4+0][r] = v.x; Bs[c4+1][r] = v.y; Bs[c4+2][r] = v.z; Bs[c4+3][r] = v.w;
        }
        __syncthreads();
        #pragma unroll
        for (int k = 0; k < 32; ++k) {
            float a[4];
            *(float4*)a = *(const float4*)&As[k][ty*4];
            float bfr[6];
            #pragma unroll
            for (int j = 0; j < 6; ++j) bfr[j] = Bs[k][tx*6 + j];
            #pragma unroll
            for (int i = 0; i < 4; ++i)
                #pragma unroll
                for (int j = 0; j < 6; ++j)
                    acc[i][j] = fmaf(a[i], bfr[j], acc[i][j]);
        }
        __syncthreads();
    }
    #pragma unroll
    for (int i = 0; i < 4; ++i)
        #pragma unroll
        for (int j = 0; j < 6; ++j)
            g_xdbl[(size_t)(m0 + ty*4 + i) * XD + tx*6 + j] = acc[i][j];
}

// ---------------------------------------------------------------------------
// delta = softplus(x_dbl[:, :64] @ dt_proj_w^T + bias), stored TRANSPOSED
// into g_dtt [B, DI, L].  M=4096, N=2048, K=64 (single k-block).
// ---------------------------------------------------------------------------
__global__ __launch_bounds__(256)
void gemm_delta(const float* __restrict__ dtw, const float* __restrict__ dtb)
{
    __shared__ float As[64][68];
    __shared__ float Bs[64][68];
    const int tid = threadIdx.x;
    const int m0 = blockIdx.y * 64, n0 = blockIdx.x * 64;
    const int tx = tid & 15, ty = tid >> 4;

    #pragma unroll
    for (int p = 0; p < 4; ++p) {
        int idx = tid + p * 256;
        int r = idx >> 4;              // 0..63
        int c4 = (idx & 15) << 2;      // 0..60
        float4 va = *(const float4*)(g_xdbl + (size_t)(m0 + r) * XD + c4);
        As[c4+0][r] = va.x; As[c4+1][r] = va.y; As[c4+2][r] = va.z; As[c4+3][r] = va.w;
        float4 vb = *(const float4*)(dtw + (size_t)(n0 + r) * DR + c4);
        Bs[c4+0][r] = vb.x; Bs[c4+1][r] = vb.y; Bs[c4+2][r] = vb.z; Bs[c4+3][r] = vb.w;
    }
    __syncthreads();

    float acc[4][4];
    #pragma unroll
    for (int i = 0; i < 4; ++i)
        #pragma unroll
        for (int j = 0; j < 4; ++j) acc[i][j] = 0.0f;

    #pragma unroll 8
    for (int k = 0; k < 64; ++k) {
        float a[4], b[4];
        *(float4*)a = *(const float4*)&As[k][ty*4];
        *(float4*)b = *(const float4*)&Bs[k][tx*4];
        #pragma unroll
        for (int i = 0; i < 4; ++i)
            #pragma unroll
            for (int j = 0; j < 4; ++j)
                acc[i][j] = fmaf(a[i], b[j], acc[i][j]);
    }

    #pragma unroll
    for (int j = 0; j < 4; ++j) {
        int n = n0 + tx*4 + j;
        float bias = dtb[n];
        #pragma unroll
        for (int i = 0; i < 4; ++i) {
            int m = m0 + ty*4 + i;
            float v = softplusf(acc[i][j] + bias);
            int bi = m >> 11;           // m / L
            int l  = m & (LL - 1);
            g_dtt[(size_t)(bi*DI + n) * LL + l] = v;
        }
    }
}

// ---------------------------------------------------------------------------
// Selective scan. Thread = (channel, 2 states). 8 lanes per channel,
// 4 channels per warp. Inputs pre-transposed to [B,DI,L]; B/C read from
// g_xdbl (L2-resident). Skip term D[d]*x folded in.
// ---------------------------------------------------------------------------
__global__ __launch_bounds__(256)
void scan_kernel(const float* __restrict__ A_log, const float* __restrict__ Dv)
{
    const int tid = threadIdx.x;
    const int ch = blockIdx.x * 32 + (tid >> 3);  // ch = b*DI + d
    const int g  = tid & 7;
    const int b  = ch / DI;
    const int d  = ch & (DI - 1);
    const int n0 = g * 2;

    const float A0 = -__expf(A_log[d*DS + n0]);
    const float A1 = -__expf(A_log[d*DS + n0 + 1]);
    const float Dd = Dv[d];

    const float* dtp  = g_dtt + (size_t)ch * LL;
    const float* xpp  = g_xpt + (size_t)ch * LL;
    const float* rowp = g_xdbl + (size_t)b * LL * XD;
    float* yp = g_yt + (size_t)ch * LL;

    float h0 = 0.0f, h1 = 0.0f;
    #pragma unroll 2
    for (int l = 0; l < LL; ++l) {
        float dt = __ldg(dtp + l);
        float xv = __ldg(xpp + l);
        const float* row = rowp + (size_t)l * XD;
        float2 Bv = *(const float2*)(row + DR + n0);
        float2 Cv = *(const float2*)(row + DR + DS + n0);
        float dtx = dt * xv;
        h0 = fmaf(__expf(dt * A0), h0, dtx * Bv.x);
        h1 = fmaf(__expf(dt * A1), h1, dtx * Bv.y);
        float y = fmaf(h0, Cv.x, h1 * Cv.y);
        y += __shfl_down_sync(0xffffffffu, y, 4, 8);
        y += __shfl_down_sync(0xffffffffu, y, 2, 8);
        y += __shfl_down_sync(0xffffffffu, y, 1, 8);
        if (g == 0) yp[l] = fmaf(Dd, xv, y);
    }
}

// ---------------------------------------------------------------------------
// g[b,l,d] = y_t[b,d,l] * silu(z[b,l,d])  (tiled transpose-multiply)
// ---------------------------------------------------------------------------
__global__ void gmul_kernel()
{
    __shared__ float sY[32][33];
    const int b = blockIdx.z, d0 = blockIdx.y * 32, l0 = blockIdx.x * 32;
    const int tid = threadIdx.x, tx = tid & 31, ty = tid >> 5;

    #pragma unroll
    for (int i = 0; i < 4; ++i) {
        int dd = ty + i * 8;
        sY[dd][tx] = g_yt[(size_t)(b*DI + d0 + dd) * LL + l0 + tx];
    }
    __syncthreads();
    #pragma unroll
    for (int i = 0; i < 4; ++i) {
        int r = ty + i * 8;
        float z = g_xz[(size_t)(b*LL + l0 + r) * XZW + DI + d0 + tx];
        g_g[(size_t)(b*LL + l0 + r) * DI + d0 + tx] = sY[tx][r] * siluf(z);
    }
}

// ---------------------------------------------------------------------------
extern "C" void kernel_launch(void* const* d_in, const int* in_sizes, int n_in,
                              void* d_out, int out_size)
{
    const float* x       = (const float*)d_in[0];
    const float* in_proj = (const float*)d_in[1];
    const float* conv_w  = (const float*)d_in[2];
    const float* conv_b  = (const float*)d_in[3];
    const float* x_proj  = (const float*)d_in[4];
    const float* dt_w    = (const float*)d_in[5];
    const float* dt_b    = (const float*)d_in[6];
    const float* A_log   = (const float*)d_in[7];
    const float* Dv      = (const float*)d_in[8];
    const float* out_w   = (const float*)d_in[9];
    float* out = (float*)d_out;

    float *xz = nullptr, *gg = nullptr;
    cudaGetSymbolAddress((void**)&xz, g_xz);
    cudaGetSymbolAddress((void**)&gg, g_g);

    // 1) xz = x @ in_proj_w^T      [4096,1024]x[4096,1024]^T -> [4096,4096]
    gemm_nt_128<<<dim3(XZW/128, NR/128), 256>>>(x, in_proj, xz, NR, XZW, DM);
    // 2) conv + silu (writes both layouts)
    conv_silu_kernel<<<dim3(LL/32, DI/32, BB), 256>>>(conv_w, conv_b);
    // 3) x_dbl = x_p @ x_proj_w^T  -> [4096, 96]
    gemm_xproj<<<NR/64, 256>>>(x_proj);
    // 4) delta = softplus(... + b), transposed to [B,DI,L]
    gemm_delta<<<dim3(DI/64, NR/64), 256>>>(dt_w, dt_b);
    // 5) selective scan (+ D*x skip term), output [B,DI,L]
    scan_kernel<<<(BB*DI*8)/256, 256>>>(A_log, Dv);
    // 6) g = y * silu(z)  -> [B,L,DI]
    gmul_kernel<<<dim3(LL/32, DI/32, BB), 256>>>();
    // 7) out = g @ out_proj_w^T -> [4096, 1024]
    gemm_nt_128<<<dim3(DM/128, NR/128), 256>>>(gg, out_w, out, NR, DM, DI);
}

// round 5
// speedup vs baseline: 1.4846x; 1.4846x over previous
#include <cuda_runtime.h>
#include <cuda_bf16.h>
#include <cstdint>
#include <math.h>

// Problem constants (fixed by reference)
#define BB 2
#define LL 2048
#define DM 1024
#define DI 2048
#define DS 16
#define DR 64
#define NR (BB*LL)     // 4096 rows (b,l)
#define XZW (2*DI)     // 4096
#define XD  96         // dt_rank + 2*d_state

// Scratch (device globals; no allocation allowed)
__device__ float g_xz  [(size_t)NR*XZW];   // in_proj output [B,L,2*DI]
__device__ float g_xp  [(size_t)NR*DI];    // conv+silu output [B,L,DI]
__device__ float g_xpt [(size_t)BB*DI*LL]; // conv+silu output transposed [B,DI,L]
__device__ float g_xdbl[(size_t)NR*XD];    // x_proj output [B,L,96]
__device__ float g_dtt [(size_t)BB*DI*LL]; // softplus(delta) transposed [B,DI,L]
__device__ float g_yt  [(size_t)BB*DI*LL]; // scan output (+D*x) [B,DI,L]
__device__ float g_g   [(size_t)NR*DI];    // y * silu(z) [B,L,DI]

// bf16 split buffers for tensor-core GEMMs
__device__ __nv_bfloat16 g_xhi [(size_t)NR*DM];
__device__ __nv_bfloat16 g_xlo [(size_t)NR*DM];
__device__ __nv_bfloat16 g_w1hi[(size_t)XZW*DM];
__device__ __nv_bfloat16 g_w1lo[(size_t)XZW*DM];
__device__ __nv_bfloat16 g_ghi [(size_t)NR*DI];
__device__ __nv_bfloat16 g_glo [(size_t)NR*DI];
__device__ __nv_bfloat16 g_w2hi[(size_t)DM*DI];
__device__ __nv_bfloat16 g_w2lo[(size_t)DM*DI];

__device__ __forceinline__ float siluf(float x) { return x / (1.0f + __expf(-x)); }
__device__ __forceinline__ float softplusf(float x) {
    return (x > 20.0f) ? x : log1pf(__expf(x));
}

// ===========================================================================
// Base-target (sm_103, no 'a') tensor path: ldmatrix + mma.sync + cp.async
// ===========================================================================
__device__ __forceinline__ uint32_t smem_u32(const void* p) {
    uint32_t a;
    asm("{ .reg .u64 t; cvta.to.shared.u64 t, %1; cvt.u32.u64 %0, t; }" : "=r"(a) : "l"(p));
    return a;
}
__device__ __forceinline__ void cpa16(uint32_t dst, const void* src) {
    asm volatile("cp.async.cg.shared.global [%0], [%1], 16;" :: "r"(dst), "l"(src));
}
__device__ __forceinline__ void ldsm4(uint32_t* r, uint32_t a) {
    asm volatile("ldmatrix.sync.aligned.m8n8.x4.shared.b16 {%0,%1,%2,%3}, [%4];"
                 : "=r"(r[0]), "=r"(r[1]), "=r"(r[2]), "=r"(r[3]) : "r"(a));
}
__device__ __forceinline__ void ldsm2(uint32_t* r, uint32_t a) {
    asm volatile("ldmatrix.sync.aligned.m8n8.x2.shared.b16 {%0,%1}, [%2];"
                 : "=r"(r[0]), "=r"(r[1]) : "r"(a));
}
__device__ __forceinline__ void mma16816(float* c, const uint32_t* a, const uint32_t* b) {
    asm volatile("mma.sync.aligned.m16n8k16.row.col.f32.bf16.bf16.f32 "
                 "{%0,%1,%2,%3}, {%4,%5,%6,%7}, {%8,%9}, {%0,%1,%2,%3};"
                 : "+f"(c[0]), "+f"(c[1]), "+f"(c[2]), "+f"(c[3])
                 : "r"(a[0]), "r"(a[1]), "r"(a[2]), "r"(a[3]), "r"(b[0]), "r"(b[1]));
}

// ===========================================================================
// Split fp32 -> bf16 hi + bf16 lo (residual)
// ===========================================================================
__global__ void split_bf16(const float* __restrict__ in, __nv_bfloat16* __restrict__ hi,
                           __nv_bfloat16* __restrict__ lo, int n4)
{
    int i = blockIdx.x * blockDim.x + threadIdx.x;
    if (i >= n4) return;
    float4 v = *(const float4*)(in + (size_t)i * 4);
    __nv_bfloat16 h0 = __float2bfloat16(v.x), h1 = __float2bfloat16(v.y);
    __nv_bfloat16 h2 = __float2bfloat16(v.z), h3 = __float2bfloat16(v.w);
    __nv_bfloat16 l0 = __float2bfloat16(v.x - __bfloat162float(h0));
    __nv_bfloat16 l1 = __float2bfloat16(v.y - __bfloat162float(h1));
    __nv_bfloat16 l2 = __float2bfloat16(v.z - __bfloat162float(h2));
    __nv_bfloat16 l3 = __float2bfloat16(v.w - __bfloat162float(h3));
    __nv_bfloat162* hp = (__nv_bfloat162*)(hi + (size_t)i * 4);
    __nv_bfloat162* lp = (__nv_bfloat162*)(lo + (size_t)i * 4);
    hp[0] = __nv_bfloat162(h0, h1); hp[1] = __nv_bfloat162(h2, h3);
    lp[0] = __nv_bfloat162(l0, l1); lp[1] = __nv_bfloat162(l2, l3);
}

// ===========================================================================
// Split-bf16 HMMA GEMM: C[M,N] = A[M,K] @ B[N,K]^T, fp32 accumulate.
// Tile 128x128, stage K=32, 8 warps (2x4), warp tile 64x32 (4x4 m16n8k16).
// cp.async double-buffered smem, 80B row pitch (conflict-free ldmatrix).
// ===========================================================================
#define APITCH 80
#define MAT_BYTES 10240            // 128 rows * 80B
#define STG_BYTES (4*MAT_BYTES)    // Ahi, Alo, Bhi, Blo
#define HM_SMEM (2*STG_BYTES)      // 81920

__global__ void __launch_bounds__(256, 1)
hmma_gemm(const __nv_bfloat16* __restrict__ Ahi, const __nv_bfloat16* __restrict__ Alo,
          const __nv_bfloat16* __restrict__ Bhi, const __nv_bfloat16* __restrict__ Blo,
          float* __restrict__ C, int N, int K)
{
    extern __shared__ char sm[];
    const uint32_t sb = smem_u32(sm);
    const int tid = threadIdx.x, lane = tid & 31, wid = tid >> 5;
    const int wm = wid >> 2, wn = wid & 3;
    const int m0 = blockIdx.y * 128, n0 = blockIdx.x * 128;
    const int nst = K >> 5;

    float acc[4][4][4];
    #pragma unroll
    for (int i = 0; i < 4; ++i)
        #pragma unroll
        for (int j = 0; j < 4; ++j)
            #pragma unroll
            for (int q = 0; q < 4; ++q) acc[i][j][q] = 0.0f;

    const int lr = tid >> 2;            // 0..63
    const int lcB = (tid & 3) * 16;     // 16B chunk byte offset within 64B kslab

    // ---- stage loader (cp.async) ----
    auto load_stage = [&](int s) {
        const uint32_t st = sb + (s & 1) * STG_BYTES;
        const int kb = (s << 5) * 2;    // byte offset along K
        #pragma unroll
        for (int p = 0; p < 2; ++p) {
            int r = lr + p * 64;
            uint32_t so = r * APITCH + lcB;
            const char* a = (const char*)(Ahi + (size_t)(m0 + r) * K) + kb + lcB;
            const char* al = (const char*)(Alo + (size_t)(m0 + r) * K) + kb + lcB;
            const char* b = (const char*)(Bhi + (size_t)(n0 + r) * K) + kb + lcB;
            const char* bl = (const char*)(Blo + (size_t)(n0 + r) * K) + kb + lcB;
            cpa16(st + so, a);
            cpa16(st + MAT_BYTES + so, al);
            cpa16(st + 2*MAT_BYTES + so, b);
            cpa16(st + 3*MAT_BYTES + so, bl);
        }
        asm volatile("cp.async.commit_group;");
    };

    load_stage(0);

    for (int s = 0; s < nst; ++s) {
        if (s + 1 < nst) {
            load_stage(s + 1);
            asm volatile("cp.async.wait_group 1;");
        } else {
            asm volatile("cp.async.wait_group 0;");
        }
        __syncthreads();

        const uint32_t st = sb + (s & 1) * STG_BYTES;
        const uint32_t aBase = st + (wm*64 + (lane & 15)) * APITCH + ((lane >> 4) * 16);
        const uint32_t bBase = st + 2*MAT_BYTES + (wn*32 + (lane & 7)) * APITCH
                             + (((lane >> 3) & 1) * 16);
        #pragma unroll
        for (int ks = 0; ks < 2; ++ks) {
            uint32_t ah[4][4], al[4][4], bh[4][2], bl[4][2];
            #pragma unroll
            for (int i = 0; i < 4; ++i) {
                ldsm4(ah[i], aBase + i * 16*APITCH + ks*32);
                ldsm4(al[i], aBase + MAT_BYTES + i * 16*APITCH + ks*32);
            }
            #pragma unroll
            for (int j = 0; j < 4; ++j) {
                ldsm2(bh[j], bBase + j * 8*APITCH + ks*32);
                ldsm2(bl[j], bBase + MAT_BYTES + j * 8*APITCH + ks*32);
            }
            #pragma unroll
            for (int i = 0; i < 4; ++i)
                #pragma unroll
                for (int j = 0; j < 4; ++j) {
                    mma16816(acc[i][j], ah[i], bh[j]);
                    mma16816(acc[i][j], ah[i], bl[j]);
                    mma16816(acc[i][j], al[i], bh[j]);
                }
        }
        __syncthreads();
    }

    // ---- epilogue: fp32 direct to global ----
    #pragma unroll
    for (int i = 0; i < 4; ++i)
        #pragma unroll
        for (int j = 0; j < 4; ++j) {
            int row = m0 + wm*64 + i*16 + (lane >> 2);
            int col = n0 + wn*32 + j*8 + (lane & 3)*2;
            *(float2*)(C + (size_t)row * N + col) =
                make_float2(acc[i][j][0], acc[i][j][1]);
            *(float2*)(C + (size_t)(row + 8) * N + col) =
                make_float2(acc[i][j][2], acc[i][j][3]);
        }
}

// ---------------------------------------------------------------------------
// Causal depthwise conv (width 4) + bias + silu over xz[:, :, 0:DI].
// ---------------------------------------------------------------------------
__global__ void conv_silu_kernel(const float* __restrict__ conv_w,
                                 const float* __restrict__ conv_b)
{
    __shared__ float sIn[35][33];
    __shared__ float sOut[32][33];
    const int b = blockIdx.z, d0 = blockIdx.y * 32, l0 = blockIdx.x * 32;
    const int tid = threadIdx.x, tx = tid & 31, ty = tid >> 5;

    for (int r = ty; r < 35; r += 8) {
        int gl = l0 + r - 3;
        sIn[r][tx] = (gl >= 0) ? g_xz[(size_t)(b*LL + gl) * XZW + d0 + tx] : 0.0f;
    }
    __syncthreads();

    float4 w = *(const float4*)(conv_w + (d0 + tx) * 4);
    float cb = conv_b[d0 + tx];
    #pragma unroll
    for (int i = 0; i < 4; ++i) {
        int r = ty + i * 8;
        float v = sIn[r][tx]*w.x + sIn[r+1][tx]*w.y + sIn[r+2][tx]*w.z + sIn[r+3][tx]*w.w + cb;
        v = siluf(v);
        sOut[r][tx] = v;
        g_xp[(size_t)(b*LL + l0 + r) * DI + d0 + tx] = v;
    }
    __syncthreads();
    #pragma unroll
    for (int i = 0; i < 4; ++i) {
        int dd = ty + i * 8;
        g_xpt[(size_t)(b*DI + d0 + dd) * LL + l0 + tx] = sOut[tx][dd];
    }
}

// ---------------------------------------------------------------------------
// x_dbl = x_p @ x_proj_w^T : [4096, 2048] x [96, 2048]^T -> [4096, 96]
// ---------------------------------------------------------------------------
__global__ __launch_bounds__(256)
void gemm_xproj(const float* __restrict__ xw)
{
    __shared__ float As[32][68];
    __shared__ float Bs[32][100];
    const int tid = threadIdx.x;
    const int m0 = blockIdx.x * 64;
    const int tx = tid & 15, ty = tid >> 4;

    float acc[4][6];
    #pragma unroll
    for (int i = 0; i < 4; ++i)
        #pragma unroll
        for (int j = 0; j < 6; ++j) acc[i][j] = 0.0f;

    for (int k0 = 0; k0 < DI; k0 += 32) {
        #pragma unroll
        for (int p = 0; p < 2; ++p) {
            int idx = tid + p * 256;
            int r = idx >> 3, c4 = (idx & 7) << 2;
            float4 v = *(const float4*)(g_xp + (size_t)(m0 + r) * DI + k0 + c4);
            As[c4+0][r] = v.x; As[c4+1][r] = v.y; As[c4+2][r] = v.z; As[c4+3][r] = v.w;
        }
        #pragma unroll
        for (int p = 0; p < 3; ++p) {
            int idx = tid + p * 256;
            int r = idx >> 3, c4 = (idx & 7) << 2;
            float4 v = *(const float4*)(xw + (size_t)r * DI + k0 + c4);
            Bs[c4+0][r] = v.x; Bs[c4+1][r] = v.y; Bs[c4+2][r] = v.z; Bs[c4+3][r] = v.w;
        }
        __syncthreads();
        #pragma unroll
        for (int k = 0; k < 32; ++k) {
            float a[4];
            *(float4*)a = *(const float4*)&As[k][ty*4];
            float bfr[6];
            #pragma unroll
            for (int j = 0; j < 6; ++j) bfr[j] = Bs[k][tx*6 + j];
            #pragma unroll
            for (int i = 0; i < 4; ++i)
                #pragma unroll
                for (int j = 0; j < 6; ++j)
                    acc[i][j] = fmaf(a[i], bfr[j], acc[i][j]);
        }
        __syncthreads();
    }
    #pragma unroll
    for (int i = 0; i < 4; ++i)
        #pragma unroll
        for (int j = 0; j < 6; ++j)
            g_xdbl[(size_t)(m0 + ty*4 + i) * XD + tx*6 + j] = acc[i][j];
}

// ---------------------------------------------------------------------------
// delta = softplus(x_dbl[:, :64] @ dt_proj_w^T + bias), stored TRANSPOSED
// ---------------------------------------------------------------------------
__global__ __launch_bounds__(256)
void gemm_delta(const float* __restrict__ dtw, const float* __restrict__ dtb)
{
    __shared__ float As[64][68];
    __shared__ float Bs[64][68];
    const int tid = threadIdx.x;
    const int m0 = blockIdx.y * 64, n0 = blockIdx.x * 64;
    const int tx = tid & 15, ty = tid >> 4;

    #pragma unroll
    for (int p = 0; p < 4; ++p) {
        int idx = tid + p * 256;
        int r = idx >> 4;
        int c4 = (idx & 15) << 2;
        float4 va = *(const float4*)(g_xdbl + (size_t)(m0 + r) * XD + c4);
        As[c4+0][r] = va.x; As[c4+1][r] = va.y; As[c4+2][r] = va.z; As[c4+3][r] = va.w;
        float4 vb = *(const float4*)(dtw + (size_t)(n0 + r) * DR + c4);
        Bs[c4+0][r] = vb.x; Bs[c4+1][r] = vb.y; Bs[c4+2][r] = vb.z; Bs[c4+3][r] = vb.w;
    }
    __syncthreads();

    float acc[4][4];
    #pragma unroll
    for (int i = 0; i < 4; ++i)
        #pragma unroll
        for (int j = 0; j < 4; ++j) acc[i][j] = 0.0f;

    #pragma unroll 8
    for (int k = 0; k < 64; ++k) {
        float a[4], b[4];
        *(float4*)a = *(const float4*)&As[k][ty*4];
        *(float4*)b = *(const float4*)&Bs[k][tx*4];
        #pragma unroll
        for (int i = 0; i < 4; ++i)
            #pragma unroll
            for (int j = 0; j < 4; ++j)
                acc[i][j] = fmaf(a[i], b[j], acc[i][j]);
    }

    #pragma unroll
    for (int j = 0; j < 4; ++j) {
        int n = n0 + tx*4 + j;
        float bias = dtb[n];
        #pragma unroll
        for (int i = 0; i < 4; ++i) {
            int m = m0 + ty*4 + i;
            float v = softplusf(acc[i][j] + bias);
            int bi = m >> 11;
            int l  = m & (LL - 1);
            g_dtt[(size_t)(bi*DI + n) * LL + l] = v;
        }
    }
}

// ---------------------------------------------------------------------------
// Selective scan. Thread = (channel, 2 states). 8 lanes per channel.
// ---------------------------------------------------------------------------
__global__ __launch_bounds__(256)
void scan_kernel(const float* __restrict__ A_log, const float* __restrict__ Dv)
{
    const int tid = threadIdx.x;
    const int ch = blockIdx.x * 32 + (tid >> 3);
    const int g  = tid & 7;
    const int b  = ch / DI;
    const int d  = ch & (DI - 1);
    const int n0 = g * 2;

    const float A0 = -__expf(A_log[d*DS + n0]);
    const float A1 = -__expf(A_log[d*DS + n0 + 1]);
    const float Dd = Dv[d];

    const float* dtp  = g_dtt + (size_t)ch * LL;
    const float* xpp  = g_xpt + (size_t)ch * LL;
    const float* rowp = g_xdbl + (size_t)b * LL * XD;
    float* yp = g_yt + (size_t)ch * LL;

    float h0 = 0.0f, h1 = 0.0f;
    #pragma unroll 2
    for (int l = 0; l < LL; ++l) {
        float dt = __ldg(dtp + l);
        float xv = __ldg(xpp + l);
        const float* row = rowp + (size_t)l * XD;
        float2 Bv = *(const float2*)(row + DR + n0);
        float2 Cv = *(const float2*)(row + DR + DS + n0);
        float dtx = dt * xv;
        h0 = fmaf(__expf(dt * A0), h0, dtx * Bv.x);
        h1 = fmaf(__expf(dt * A1), h1, dtx * Bv.y);
        float y = fmaf(h0, Cv.x, h1 * Cv.y);
        y += __shfl_down_sync(0xffffffffu, y, 4, 8);
        y += __shfl_down_sync(0xffffffffu, y, 2, 8);
        y += __shfl_down_sync(0xffffffffu, y, 1, 8);
        if (g == 0) yp[l] = fmaf(Dd, xv, y);
    }
}

// ---------------------------------------------------------------------------
// g[b,l,d] = y_t[b,d,l] * silu(z[b,l,d])
// ---------------------------------------------------------------------------
__global__ void gmul_kernel()
{
    __shared__ float sY[32][33];
    const int b = blockIdx.z, d0 = blockIdx.y * 32, l0 = blockIdx.x * 32;
    const int tid = threadIdx.x, tx = tid & 31, ty = tid >> 5;

    #pragma unroll
    for (int i = 0; i < 4; ++i) {
        int dd = ty + i * 8;
        sY[dd][tx] = g_yt[(size_t)(b*DI + d0 + dd) * LL + l0 + tx];
    }
    __syncthreads();
    #pragma unroll
    for (int i = 0; i < 4; ++i) {
        int r = ty + i * 8;
        float z = g_xz[(size_t)(b*LL + l0 + r) * XZW + DI + d0 + tx];
        g_g[(size_t)(b*LL + l0 + r) * DI + d0 + tx] = sY[tx][r] * siluf(z);
    }
}

// ---------------------------------------------------------------------------
extern "C" void kernel_launch(void* const* d_in, const int* in_sizes, int n_in,
                              void* d_out, int out_size)
{
    const float* x       = (const float*)d_in[0];
    const float* in_proj = (const float*)d_in[1];
    const float* conv_w  = (const float*)d_in[2];
    const float* conv_b  = (const float*)d_in[3];
    const float* x_proj  = (const float*)d_in[4];
    const float* dt_w    = (const float*)d_in[5];
    const float* dt_b    = (const float*)d_in[6];
    const float* A_log   = (const float*)d_in[7];
    const float* Dv      = (const float*)d_in[8];
    const float* out_w   = (const float*)d_in[9];
    float* out = (float*)d_out;

    float *xz = nullptr, *gg = nullptr;
    __nv_bfloat16 *xhi, *xlo, *w1hi, *w1lo, *ghi, *glo, *w2hi, *w2lo;
    cudaGetSymbolAddress((void**)&xz,   g_xz);
    cudaGetSymbolAddress((void**)&gg,   g_g);
    cudaGetSymbolAddress((void**)&xhi,  g_xhi);
    cudaGetSymbolAddress((void**)&xlo,  g_xlo);
    cudaGetSymbolAddress((void**)&w1hi, g_w1hi);
    cudaGetSymbolAddress((void**)&w1lo, g_w1lo);
    cudaGetSymbolAddress((void**)&ghi,  g_ghi);
    cudaGetSymbolAddress((void**)&glo,  g_glo);
    cudaGetSymbolAddress((void**)&w2hi, g_w2hi);
    cudaGetSymbolAddress((void**)&w2lo, g_w2lo);

    cudaFuncSetAttribute(hmma_gemm, cudaFuncAttributeMaxDynamicSharedMemorySize, HM_SMEM);

    // 0) split inputs/weights to bf16 hi/lo
    split_bf16<<<(NR*DM/4 + 255)/256, 256>>>(x, xhi, xlo, NR*DM/4);
    split_bf16<<<(XZW*DM/4 + 255)/256, 256>>>(in_proj, w1hi, w1lo, XZW*DM/4);
    // 1) xz = x @ in_proj_w^T  (HMMA split-bf16 3-pass) -> [4096, 4096]
    hmma_gemm<<<dim3(XZW/128, NR/128), 256, HM_SMEM>>>(xhi, xlo, w1hi, w1lo, xz, XZW, DM);
    // 2) conv + silu
    conv_silu_kernel<<<dim3(LL/32, DI/32, BB), 256>>>(conv_w, conv_b);
    // 3) x_dbl = x_p @ x_proj_w^T
    gemm_xproj<<<NR/64, 256>>>(x_proj);
    // 4) delta = softplus(... + b), transposed
    gemm_delta<<<dim3(DI/64, NR/64), 256>>>(dt_w, dt_b);
    // 5) selective scan
    scan_kernel<<<(BB*DI*8)/256, 256>>>(A_log, Dv);
    // 6) g = y * silu(z)
    gmul_kernel<<<dim3(LL/32, DI/32, BB), 256>>>();
    // 7) split g and out_w, then out = g @ out_proj_w^T (HMMA)
    split_bf16<<<(NR*DI/4 + 255)/256, 256>>>(gg, ghi, glo, NR*DI/4);
    split_bf16<<<(DM*DI/4 + 255)/256, 256>>>(out_w, w2hi, w2lo, DM*DI/4);
    hmma_gemm<<<dim3(DM/128, NR/128), 256, HM_SMEM>>>(ghi, glo, w2hi, w2lo, out, DM, DI);
}